// round 11
// baseline (speedup 1.0000x reference)
#include <cuda_runtime.h>
#include <cuda_fp16.h>
#include <cstdint>

// Problem constants
#define BDIM 1024
#define LDIM 2
#define DDIM 1024
#define FDIM 32768
#define KENC 2048
#define NSPLIT 16
#define KSPLIT (FDIM / NSPLIT)          // 2048

// Tiling: CTA 128x128, 4 warps (2m x 2n), warp tile 64x64, BK=64 halves
#define STAGES 3
#define BK 64
#define THREADS 128
#define A_STAGE_BYTES (128 * BK * 2)    // 16384
#define B_STAGE_BYTES (BK * 128 * 2)    // 16384
#define STAGE_BYTES (A_STAGE_BYTES + B_STAGE_BYTES)
#define SMEM_DYN (STAGES * STAGE_BYTES) // 98304

// Scratch (device globals: allocation-guard safe)
__device__ __half g_fh [(size_t)BDIM * FDIM];          // 64 MB encoder output (fp16)
__device__ __half g_xh [(size_t)BDIM * KENC];          // 4 MB
__device__ __half g_weh[(size_t)KENC * FDIM];          // 128 MB
__device__ __half g_wdh[(size_t)LDIM * FDIM * DDIM];   // 128 MB (converted INSIDE enc)
__device__ float  g_partial[(size_t)NSPLIT * BDIM * KENC]; // 128 MB split-K partials

// ---------------------------------------------------------------------------
// helpers
// ---------------------------------------------------------------------------
__device__ __forceinline__ uint32_t smem_u32(const void* p) {
    uint32_t a;
    asm("{ .reg .u64 t; cvta.to.shared.u64 t, %1; cvt.u32.u64 %0, t; }" : "=r"(a) : "l"(p));
    return a;
}

__device__ __forceinline__ void cp16(uint32_t dst, const void* src) {
    asm volatile("cp.async.cg.shared.global [%0], [%1], 16;" :: "r"(dst), "l"(src));
}

#define LDSM4(r, addr)                                                          \
    asm volatile("ldmatrix.sync.aligned.m8n8.x4.shared.b16 {%0,%1,%2,%3}, [%4];" \
        : "=r"((r)[0]), "=r"((r)[1]), "=r"((r)[2]), "=r"((r)[3]) : "r"(addr))

#define LDSM4T(r, addr)                                                         \
    asm volatile("ldmatrix.sync.aligned.m8n8.x4.trans.shared.b16 {%0,%1,%2,%3}, [%4];" \
        : "=r"((r)[0]), "=r"((r)[1]), "=r"((r)[2]), "=r"((r)[3]) : "r"(addr))

__device__ __forceinline__ void mma_f16(float c[4], const uint32_t a[4],
                                        const uint32_t b[2]) {
    asm volatile(
        "mma.sync.aligned.m16n8k16.row.col.f32.f16.f16.f32 "
        "{%0,%1,%2,%3}, {%4,%5,%6,%7}, {%8,%9}, {%0,%1,%2,%3};"
        : "+f"(c[0]), "+f"(c[1]), "+f"(c[2]), "+f"(c[3])
        : "r"(a[0]), "r"(a[1]), "r"(a[2]), "r"(a[3]), "r"(b[0]), "r"(b[1]));
}

__device__ __forceinline__ uint4 cvt8(float4 a, float4 b) {
    __half2 h0 = __float22half2_rn(make_float2(a.x, a.y));
    __half2 h1 = __float22half2_rn(make_float2(a.z, a.w));
    __half2 h2 = __float22half2_rn(make_float2(b.x, b.y));
    __half2 h3 = __float22half2_rn(make_float2(b.z, b.w));
    uint4 o;
    o.x = *reinterpret_cast<uint32_t*>(&h0);
    o.y = *reinterpret_cast<uint32_t*>(&h1);
    o.z = *reinterpret_cast<uint32_t*>(&h2);
    o.w = *reinterpret_cast<uint32_t*>(&h3);
    return o;
}

// ---------------------------------------------------------------------------
// fp32 -> fp16 convert (grid-stride, 8 elems/thread/iter)
// ---------------------------------------------------------------------------
__global__ void __launch_bounds__(256) cvt_kernel(
    const float* __restrict__ src, __half* __restrict__ dst, int n8)
{
    int stride = gridDim.x * blockDim.x;
    for (int i = blockIdx.x * blockDim.x + threadIdx.x; i < n8; i += stride) {
        float4 a = reinterpret_cast<const float4*>(src)[2 * i];
        float4 b = reinterpret_cast<const float4*>(src)[2 * i + 1];
        reinterpret_cast<uint4*>(dst)[i] = cvt8(a, b);
    }
}

// ---------------------------------------------------------------------------
// fp16 GEMM core: C[128,128] = A[128,K] (k-major) * B[K,128] (k-major rows)
// 4 warps (2m x 2n), warp tile 64x64, mma m16n8k16, ldmatrix operands.
// BK=64, 3-stage cp.async pipeline.
// MODE 0: enc (bias + relu, __half out) + fused W_dec fp32->fp16 conversion
//         (1 x 8-elem unit per thread per k-iteration; kTiles MUST be 32)
// MODE 1: dec (raw fp32 out)
// SMEM swizzles (conflict-free for cp.async writes AND all ldmatrix phases):
//   A[r][chunk c]  at r*128 + 16*(c  ^ (r&7))          (8 chunks/row)
//   B[k][chunk nc] at k*256 + 16*(nc ^ (k&7))          (16 chunks/row)
// ---------------------------------------------------------------------------
template <int MODE>
__device__ __forceinline__ void gemm_f16(
    const __half* __restrict__ A, int lda,
    const __half* __restrict__ B, int ldb,
    void* __restrict__ Cv, int ldc,
    int kTiles, const float* __restrict__ bias,
    const float4* __restrict__ cvt_src, uint4* __restrict__ cvt_dst)
{
    extern __shared__ char smem_raw[];
    const uint32_t base = smem_u32(smem_raw);

    const int tid  = threadIdx.x;
    const int lane = tid & 31;
    const int warp = tid >> 5;          // 0..3
    const int wm = (warp & 1) << 6;     // 0 / 64
    const int wn = (warp >> 1) << 6;    // 0 / 64
    const int ty = lane >> 2;
    const int tc = lane & 3;
    const int lr8 = (lane & 7) + ((lane >> 3) & 1) * 8;  // 0..15
    const int g2  = lane >> 4;                            // 0..1

    float acc[4][8][4];
#pragma unroll
    for (int mt = 0; mt < 4; mt++)
#pragma unroll
        for (int nt = 0; nt < 8; nt++)
#pragma unroll
            for (int i = 0; i < 4; i++) acc[mt][nt][i] = 0.f;

    // Loader: strided chunks (BK=64 makes per-thread columns constant).
    // A: chunk t covers row r0+16t, col c ; B: row k0+8t, col nc.
    const int ca = tid & 7, r0 = tid >> 3;        // A col-chunk, base row
    const int nb = tid & 15, k0 = tid >> 4;       // B col-chunk, base k
    const uint32_t soffA = r0 * 128 + 16 * (ca ^ (r0 & 7));
    const uint32_t soffB = A_STAGE_BYTES + k0 * 256 + 16 * (nb ^ (k0 & 7));
    const __half* gpA = A + (size_t)r0 * lda + ca * 8;
    const __half* gpB = B + (size_t)k0 * ldb + nb * 8;
    const size_t stepA = (size_t)16 * lda;
    const size_t stepB = (size_t)8 * ldb;

#define LOAD_STAGE(s)                                                           \
    do {                                                                        \
        const uint32_t sb_ = base + (s) * STAGE_BYTES;                          \
        _Pragma("unroll")                                                       \
        for (int t = 0; t < 8; t++)                                             \
            cp16(sb_ + soffA + t * 2048, gpA + (size_t)t * stepA);              \
        _Pragma("unroll")                                                       \
        for (int t = 0; t < 8; t++)                                             \
            cp16(sb_ + soffB + t * 2048, gpB + (size_t)t * stepB);              \
        gpA += BK; gpB += (size_t)BK * ldb;                                     \
        asm volatile("cp.async.commit_group;");                                 \
    } while (0)

    // ldmatrix bases. A: row = wm + mt*16 + lr8 ; kc = ks*2 + g2.
    uint32_t arow[4], ar7[4];
#pragma unroll
    for (int mt = 0; mt < 4; mt++) {
        const int row = wm + mt * 16 + lr8;
        arow[mt] = row * 128;
        ar7[mt]  = row & 7;
    }
    // B: kb = ks*16 + lr8 ; nc = (wn>>3) + np*2 + g2 ; kb&7 == lr8&7 (const).
    uint32_t bbase[4];
#pragma unroll
    for (int np = 0; np < 4; np++) {
        const int nc = (wn >> 3) + np * 2 + g2;
        bbase[np] = A_STAGE_BYTES + lr8 * 256 + 16 * (nc ^ (lr8 & 7));
    }

    // Prologue: fill STAGES-1 = 2 stages
#pragma unroll
    for (int p = 0; p < STAGES - 1; p++) LOAD_STAGE(p);

    int s = 0;  // current stage
    for (int kt = 0; kt < kTiles; kt++) {
        asm volatile("cp.async.wait_group %0;" :: "n"(STAGES - 2));
        __syncthreads();

        // Refill stage (kt+2)%3 — read at iter kt-1, finished before barrier.
        if (kt + STAGES - 1 < kTiles) {
            int rs = s + STAGES - 1; if (rs >= STAGES) rs -= STAGES;
            LOAD_STAGE(rs);
        } else {
            asm volatile("cp.async.commit_group;");
        }

        // Fused W_dec conversion (enc only): 1 unit of 8 elems per thread.
        if (MODE == 0) {
            const int u = kt * THREADS + tid;
            const float4 a4 = cvt_src[2 * u];
            const float4 b4 = cvt_src[2 * u + 1];
            cvt_dst[u] = cvt8(a4, b4);
        }

        const uint32_t sb = base + s * STAGE_BYTES;
#pragma unroll
        for (int ks = 0; ks < 4; ks++) {
            uint32_t af[4][4];
#pragma unroll
            for (int mt = 0; mt < 4; mt++)
                LDSM4(af[mt], sb + arow[mt] + 16 * ((ks * 2 + g2) ^ ar7[mt]));
            uint32_t bf[8][2];
#pragma unroll
            for (int np = 0; np < 4; np++) {
                uint32_t r[4];
                LDSM4T(r, sb + bbase[np] + ks * 4096);
                bf[np * 2][0]     = r[0]; bf[np * 2][1]     = r[1];
                bf[np * 2 + 1][0] = r[2]; bf[np * 2 + 1][1] = r[3];
            }
#pragma unroll
            for (int mt = 0; mt < 4; mt++)
#pragma unroll
                for (int nt = 0; nt < 8; nt++)
                    mma_f16(acc[mt][nt], af[mt], bf[nt]);
        }
        if (++s == STAGES) s = 0;
    }
#undef LOAD_STAGE

    // Epilogue. acc layout: c0,c1 -> (row ty, n 2tc,2tc+1); c2,c3 -> row ty+8.
#pragma unroll
    for (int mt = 0; mt < 4; mt++) {
#pragma unroll
        for (int nt = 0; nt < 8; nt++) {
            const int r = wm + mt * 16 + ty;
            const int c = wn + nt * 8 + tc * 2;
            float v0 = acc[mt][nt][0], v1 = acc[mt][nt][1];
            float v2 = acc[mt][nt][2], v3 = acc[mt][nt][3];
            if (MODE == 0) {
                const float b0 = bias[c], b1 = bias[c + 1];
                v0 = fmaxf(v0 + b0, 0.f); v1 = fmaxf(v1 + b1, 0.f);
                v2 = fmaxf(v2 + b0, 0.f); v3 = fmaxf(v3 + b1, 0.f);
                __half* C = (__half*)Cv;
                *(__half2*)(C + (size_t)r * ldc + c) =
                    __float22half2_rn(make_float2(v0, v1));
                *(__half2*)(C + (size_t)(r + 8) * ldc + c) =
                    __float22half2_rn(make_float2(v2, v3));
            } else {
                float* C = (float*)Cv;
                *(float2*)(C + (size_t)r * ldc + c)       = make_float2(v0, v1);
                *(float2*)(C + (size_t)(r + 8) * ldc + c) = make_float2(v2, v3);
            }
        }
    }
}

// ---------------------------------------------------------------------------
// Encoder: f = relu(x @ W_enc + b_enc) -> fp16, PLUS fused W_dec fp32->fp16.
// grid (8 m fastest, 256 n) ; each CTA converts 32768 W_dec elems.
// ---------------------------------------------------------------------------
__global__ void __launch_bounds__(THREADS, 2) enc_kernel(
    const float* __restrict__ benc, const float* __restrict__ Wdec)
{
    const int m = blockIdx.x, n = blockIdx.y;
    const size_t bid = blockIdx.x + (size_t)gridDim.x * blockIdx.y;   // 0..2047
    gemm_f16<0>(g_xh + (size_t)m * 128 * KENC, KENC,
                g_weh + (size_t)n * 128, FDIM,
                g_fh + (size_t)m * 128 * FDIM + (size_t)n * 128, FDIM,
                KENC / BK, benc + n * 128,
                reinterpret_cast<const float4*>(Wdec) + bid * 8192,
                reinterpret_cast<uint4*>(g_wdh) + bid * 4096);
}

// ---------------------------------------------------------------------------
// Decoder split-K: partial[s] += f[:, sK:(s+1)K] @ W_dec. grid (8 m, 16 n, 16 s)
// n tile: l = n>>3, d-block = n&7 (128-wide tiles never straddle l)
// ---------------------------------------------------------------------------
__global__ void __launch_bounds__(THREADS, 2) dec_kernel()
{
    const int m = blockIdx.x, n = blockIdx.y, split = blockIdx.z;
    const int l = n >> 3, db = n & 7;
    gemm_f16<1>(g_fh + (size_t)m * 128 * FDIM + (size_t)split * KSPLIT, FDIM,
                g_wdh + (size_t)l * FDIM * DDIM + (size_t)split * KSPLIT * DDIM
                      + (size_t)db * 128, DDIM,
                g_partial + (size_t)split * BDIM * KENC
                          + (size_t)m * 128 * KENC + (size_t)n * 128, KENC,
                KSPLIT / BK, nullptr, nullptr, nullptr);
}

// ---------------------------------------------------------------------------
// Reduce: out[b, n] = b_dec[n] + sum_s partial[s][b][n]
// ---------------------------------------------------------------------------
__global__ void __launch_bounds__(256) reduce_kernel(
    const float* __restrict__ bdec, float* __restrict__ out)
{
    const int i = blockIdx.x * blockDim.x + threadIdx.x;  // float4 index
    float4 s = reinterpret_cast<const float4*>(bdec)[i & 511];
#pragma unroll
    for (int p = 0; p < NSPLIT; p++) {
        float4 v = reinterpret_cast<const float4*>(g_partial)[(size_t)p * 524288 + i];
        s.x += v.x; s.y += v.y; s.z += v.z; s.w += v.w;
    }
    reinterpret_cast<float4*>(out)[i] = s;
}

// ---------------------------------------------------------------------------
extern "C" void kernel_launch(void* const* d_in, const int* in_sizes, int n_in,
                              void* d_out, int out_size)
{
    const float* x    = (const float*)d_in[0];   // [1024, 2, 1024]
    const float* Wenc = (const float*)d_in[1];   // [2, 1024, 32768]
    const float* benc = (const float*)d_in[2];   // [32768]
    const float* Wdec = (const float*)d_in[3];   // [2, 32768, 1024]
    const float* bdec = (const float*)d_in[4];   // [2, 1024]
    float* out = (float*)d_out;                  // [1024, 2, 1024]

    __half* gx; __half* gwe;
    cudaGetSymbolAddress((void**)&gx,  g_xh);
    cudaGetSymbolAddress((void**)&gwe, g_weh);

    cudaFuncSetAttribute(enc_kernel, cudaFuncAttributeMaxDynamicSharedMemorySize, SMEM_DYN);
    cudaFuncSetAttribute(dec_kernel, cudaFuncAttributeMaxDynamicSharedMemorySize, SMEM_DYN);

    // fp32 -> fp16 (RN): x and W_enc up front; W_dec is fused into enc_kernel.
    cvt_kernel<<<512,  256>>>(x,    gx,  (BDIM * KENC) / 8);
    cvt_kernel<<<2048, 256>>>(Wenc, gwe, (KENC * FDIM) / 8);

    enc_kernel<<<dim3(BDIM / 128, FDIM / 128), THREADS, SMEM_DYN>>>(benc, Wdec);
    dec_kernel<<<dim3(BDIM / 128, KENC / 128, NSPLIT), THREADS, SMEM_DYN>>>();
    reduce_kernel<<<(BDIM * KENC / 4) / 256, 256>>>(bdec, out);
}

// round 12
// speedup vs baseline: 1.0236x; 1.0236x over previous
#include <cuda_runtime.h>
#include <cuda_fp16.h>
#include <cstdint>

// Problem constants
#define BDIM 1024
#define LDIM 2
#define DDIM 1024
#define FDIM 32768
#define KENC 2048
#define NSPLIT 16
#define KSPLIT (FDIM / NSPLIT)          // 2048

// Tiling: CTA 128x128, 4 warps (2m x 2n), warp tile 64x64, BK=32 halves
// (exact R10 configuration — verified 702.5us / enc tensor 79.7%)
#define STAGES 4
#define BK 32
#define THREADS 128
#define A_STAGE_BYTES (128 * BK * 2)    // 8192
#define B_STAGE_BYTES (BK * 128 * 2)    // 8192
#define STAGE_BYTES (A_STAGE_BYTES + B_STAGE_BYTES)
#define SMEM_DYN (STAGES * STAGE_BYTES) // 65536

// Scratch (device globals: allocation-guard safe)
__device__ __half g_fh [(size_t)BDIM * FDIM];          // 64 MB encoder output (fp16)
__device__ __half g_xh [(size_t)BDIM * KENC];          // 4 MB
__device__ __half g_weh[(size_t)KENC * FDIM];          // 128 MB
__device__ __half g_wdh[(size_t)LDIM * FDIM * DDIM];   // 128 MB (converted by enc's x==8 CTA column)
__device__ float  g_partial[(size_t)NSPLIT * BDIM * KENC]; // 128 MB split-K partials

// ---------------------------------------------------------------------------
// helpers
// ---------------------------------------------------------------------------
__device__ __forceinline__ uint32_t smem_u32(const void* p) {
    uint32_t a;
    asm("{ .reg .u64 t; cvta.to.shared.u64 t, %1; cvt.u32.u64 %0, t; }" : "=r"(a) : "l"(p));
    return a;
}

__device__ __forceinline__ void cp16(uint32_t dst, const void* src) {
    asm volatile("cp.async.cg.shared.global [%0], [%1], 16;" :: "r"(dst), "l"(src));
}

#define LDSM4(r, addr)                                                          \
    asm volatile("ldmatrix.sync.aligned.m8n8.x4.shared.b16 {%0,%1,%2,%3}, [%4];" \
        : "=r"((r)[0]), "=r"((r)[1]), "=r"((r)[2]), "=r"((r)[3]) : "r"(addr))

#define LDSM4T(r, addr)                                                         \
    asm volatile("ldmatrix.sync.aligned.m8n8.x4.trans.shared.b16 {%0,%1,%2,%3}, [%4];" \
        : "=r"((r)[0]), "=r"((r)[1]), "=r"((r)[2]), "=r"((r)[3]) : "r"(addr))

__device__ __forceinline__ void mma_f16(float c[4], const uint32_t a[4],
                                        const uint32_t b[2]) {
    asm volatile(
        "mma.sync.aligned.m16n8k16.row.col.f32.f16.f16.f32 "
        "{%0,%1,%2,%3}, {%4,%5,%6,%7}, {%8,%9}, {%0,%1,%2,%3};"
        : "+f"(c[0]), "+f"(c[1]), "+f"(c[2]), "+f"(c[3])
        : "r"(a[0]), "r"(a[1]), "r"(a[2]), "r"(a[3]), "r"(b[0]), "r"(b[1]));
}

__device__ __forceinline__ uint4 cvt8(float4 a, float4 b) {
    __half2 h0 = __float22half2_rn(make_float2(a.x, a.y));
    __half2 h1 = __float22half2_rn(make_float2(a.z, a.w));
    __half2 h2 = __float22half2_rn(make_float2(b.x, b.y));
    __half2 h3 = __float22half2_rn(make_float2(b.z, b.w));
    uint4 o;
    o.x = *reinterpret_cast<uint32_t*>(&h0);
    o.y = *reinterpret_cast<uint32_t*>(&h1);
    o.z = *reinterpret_cast<uint32_t*>(&h2);
    o.w = *reinterpret_cast<uint32_t*>(&h3);
    return o;
}

// ---------------------------------------------------------------------------
// fp32 -> fp16 convert (grid-stride, 8 elems/thread/iter)
// ---------------------------------------------------------------------------
__global__ void __launch_bounds__(256) cvt_kernel(
    const float* __restrict__ src, __half* __restrict__ dst, int n8)
{
    int stride = gridDim.x * blockDim.x;
    for (int i = blockIdx.x * blockDim.x + threadIdx.x; i < n8; i += stride) {
        float4 a = reinterpret_cast<const float4*>(src)[2 * i];
        float4 b = reinterpret_cast<const float4*>(src)[2 * i + 1];
        reinterpret_cast<uint4*>(dst)[i] = cvt8(a, b);
    }
}

// ---------------------------------------------------------------------------
// fp16 GEMM core: C[128,128] = A[128,K] (k-major) * B[K,128] (k-major rows)
// 4 warps (2m x 2n), warp tile 64x64, mma m16n8k16, ldmatrix operands.
// MODE 0: enc (fp32 bias + relu, __half output)
// MODE 1: dec (raw fp32 output)
// SMEM swizzles (conflict-free for cp.async writes AND all ldmatrix phases):
//   A[r][chunk c]  at r*64  + 16*(c  ^ ((r>>1)&3))     (4 chunks/row)
//   B[k][chunk nc] at k*256 + 16*(nc ^ (k&7))          (16 chunks/row)
// ---------------------------------------------------------------------------
template <int MODE>
__device__ __forceinline__ void gemm_f16(
    const __half* __restrict__ A, int lda,
    const __half* __restrict__ B, int ldb,
    void* __restrict__ Cv, int ldc,
    int kTiles, const float* __restrict__ bias)
{
    extern __shared__ char smem_raw[];
    const uint32_t base = smem_u32(smem_raw);

    const int tid  = threadIdx.x;
    const int lane = tid & 31;
    const int warp = tid >> 5;          // 0..3
    const int wm = (warp & 1) << 6;     // 0 / 64
    const int wn = (warp >> 1) << 6;    // 0 / 64
    const int ty = lane >> 2;
    const int tc = lane & 3;
    const int lr = lane & 7;
    const int g  = lane >> 3;           // ldmatrix lane group 0..3

    float acc[4][8][4];
#pragma unroll
    for (int mt = 0; mt < 4; mt++)
#pragma unroll
        for (int nt = 0; nt < 8; nt++)
#pragma unroll
            for (int i = 0; i < 4; i++) acc[mt][nt][i] = 0.f;

    // Loader precompute: 1024 16B-chunks/stage, 8 per thread. Pointers advance.
    uint32_t soff[8]; const __half* gp[8]; size_t gstep[8];
#pragma unroll
    for (int t = 0; t < 8; t++) {
        const int cid = tid + t * THREADS;
        if (cid < 512) {                       // A: [r 0..127][c 0..3]
            const int r = cid >> 2, c = cid & 3;
            soff[t]  = r * 64 + 16 * (c ^ ((r >> 1) & 3));
            gp[t]    = A + (size_t)r * lda + c * 8;
            gstep[t] = BK;
        } else {                               // B: [k 0..31][nc 0..15]
            const int b = cid - 512;
            const int k = b >> 4, nc = b & 15;
            soff[t]  = A_STAGE_BYTES + k * 256 + 16 * (nc ^ (k & 7));
            gp[t]    = B + (size_t)k * ldb + nc * 8;
            gstep[t] = (size_t)BK * ldb;
        }
    }

    // ldmatrix per-lane offsets (stage-relative), precomputed.
    uint32_t aoff[2][4], boff[2][4];
#pragma unroll
    for (int ks = 0; ks < 2; ks++) {
#pragma unroll
        for (int mt = 0; mt < 4; mt++) {
            const int row = wm + mt * 16 + lr + (g & 1) * 8;
            const int kc  = ks * 2 + (g >> 1);
            aoff[ks][mt] = row * 64 + 16 * (kc ^ ((row >> 1) & 3));
        }
#pragma unroll
        for (int np = 0; np < 4; np++) {
            const int k  = ks * 16 + lr + (g & 1) * 8;
            const int nc = (wn >> 3) + np * 2 + (g >> 1);
            boff[ks][np] = A_STAGE_BYTES + k * 256 + 16 * (nc ^ (k & 7));
        }
    }

#define LOAD_STAGE(s)                                                           \
    do {                                                                        \
        const uint32_t sb_ = base + (s) * STAGE_BYTES;                          \
        _Pragma("unroll")                                                       \
        for (int t = 0; t < 8; t++) {                                           \
            cp16(sb_ + soff[t], gp[t]);                                         \
            gp[t] += gstep[t];                                                  \
        }                                                                       \
        asm volatile("cp.async.commit_group;");                                 \
    } while (0)

    // Prologue: fill STAGES-1 = 3 stages
#pragma unroll
    for (int p = 0; p < STAGES - 1; p++) LOAD_STAGE(p);

    for (int kt = 0; kt < kTiles; kt++) {
        asm volatile("cp.async.wait_group %0;" :: "n"(STAGES - 2));
        __syncthreads();

        // Refill stage (kt-1)&3 — its readers finished before the barrier.
        if (kt + STAGES - 1 < kTiles) {
            LOAD_STAGE((kt + STAGES - 1) & (STAGES - 1));
        } else {
            asm volatile("cp.async.commit_group;");
        }

        const uint32_t sb = base + (kt & (STAGES - 1)) * STAGE_BYTES;
#pragma unroll
        for (int ks = 0; ks < 2; ks++) {
            uint32_t af[4][4];
#pragma unroll
            for (int mt = 0; mt < 4; mt++) LDSM4(af[mt], sb + aoff[ks][mt]);
            uint32_t bf[8][2];
#pragma unroll
            for (int np = 0; np < 4; np++) {
                uint32_t r[4];
                LDSM4T(r, sb + boff[ks][np]);
                bf[np * 2][0]     = r[0]; bf[np * 2][1]     = r[1];
                bf[np * 2 + 1][0] = r[2]; bf[np * 2 + 1][1] = r[3];
            }
#pragma unroll
            for (int mt = 0; mt < 4; mt++)
#pragma unroll
                for (int nt = 0; nt < 8; nt++)
                    mma_f16(acc[mt][nt], af[mt], bf[nt]);
        }
    }
#undef LOAD_STAGE

    // Epilogue. acc layout: c0,c1 -> (row ty, n 2tc,2tc+1); c2,c3 -> row ty+8.
#pragma unroll
    for (int mt = 0; mt < 4; mt++) {
#pragma unroll
        for (int nt = 0; nt < 8; nt++) {
            const int r = wm + mt * 16 + ty;
            const int c = wn + nt * 8 + tc * 2;
            float v0 = acc[mt][nt][0], v1 = acc[mt][nt][1];
            float v2 = acc[mt][nt][2], v3 = acc[mt][nt][3];
            if (MODE == 0) {
                const float b0 = bias[c], b1 = bias[c + 1];
                v0 = fmaxf(v0 + b0, 0.f); v1 = fmaxf(v1 + b1, 0.f);
                v2 = fmaxf(v2 + b0, 0.f); v3 = fmaxf(v3 + b1, 0.f);
                __half* C = (__half*)Cv;
                *(__half2*)(C + (size_t)r * ldc + c) =
                    __float22half2_rn(make_float2(v0, v1));
                *(__half2*)(C + (size_t)(r + 8) * ldc + c) =
                    __float22half2_rn(make_float2(v2, v3));
            } else {
                float* C = (float*)Cv;
                *(float2*)(C + (size_t)r * ldc + c)       = make_float2(v0, v1);
                *(float2*)(C + (size_t)(r + 8) * ldc + c) = make_float2(v2, v3);
            }
        }
    }
}

// ---------------------------------------------------------------------------
// Encoder: f = relu(x @ W_enc + b_enc) -> fp16. grid (9 m-fastest, 256 n).
//   x < 8 : GEMM tile (m = x), identical to R10.
//   x == 8: W_dec fp32->fp16 streaming conversion (256 CTAs, interleaved
//           1-in-9 through the CTA schedule so they overlap the GEMM and
//           use enc's idle DRAM bandwidth).
// ---------------------------------------------------------------------------
__global__ void __launch_bounds__(THREADS, 2) enc_kernel(
    const float* __restrict__ benc, const float* __restrict__ Wdec)
{
    if (blockIdx.x == 8) {
        // 8,388,608 uint4 units total; 256 CTAs x 128 threads x 256 units.
        const float4* src = reinterpret_cast<const float4*>(Wdec);
        uint4* dst = reinterpret_cast<uint4*>(g_wdh);
        const int u0 = blockIdx.y * 32768 + threadIdx.x;
#pragma unroll 4
        for (int t = 0; t < 256; t++) {
            const int u = u0 + t * THREADS;
            const float4 a = src[2 * u];
            const float4 b = src[2 * u + 1];
            dst[u] = cvt8(a, b);
        }
        return;
    }
    const int m = blockIdx.x, n = blockIdx.y;
    gemm_f16<0>(g_xh + (size_t)m * 128 * KENC, KENC,
                g_weh + (size_t)n * 128, FDIM,
                g_fh + (size_t)m * 128 * FDIM + (size_t)n * 128, FDIM,
                KENC / BK, benc + n * 128);
}

// ---------------------------------------------------------------------------
// Decoder split-K: partial[s] += f[:, sK:(s+1)K] @ W_dec. grid (8 m, 16 n, 16 s)
// n tile: l = n>>3, d-block = n&7 (128-wide tiles never straddle l)
// ---------------------------------------------------------------------------
__global__ void __launch_bounds__(THREADS, 2) dec_kernel()
{
    const int m = blockIdx.x, n = blockIdx.y, split = blockIdx.z;
    const int l = n >> 3, db = n & 7;
    gemm_f16<1>(g_fh + (size_t)m * 128 * FDIM + (size_t)split * KSPLIT, FDIM,
                g_wdh + (size_t)l * FDIM * DDIM + (size_t)split * KSPLIT * DDIM
                      + (size_t)db * 128, DDIM,
                g_partial + (size_t)split * BDIM * KENC
                          + (size_t)m * 128 * KENC + (size_t)n * 128, KENC,
                KSPLIT / BK, nullptr);
}

// ---------------------------------------------------------------------------
// Reduce: out[b, n] = b_dec[n] + sum_s partial[s][b][n]
// ---------------------------------------------------------------------------
__global__ void __launch_bounds__(256) reduce_kernel(
    const float* __restrict__ bdec, float* __restrict__ out)
{
    const int i = blockIdx.x * blockDim.x + threadIdx.x;  // float4 index
    float4 s = reinterpret_cast<const float4*>(bdec)[i & 511];
#pragma unroll
    for (int p = 0; p < NSPLIT; p++) {
        float4 v = reinterpret_cast<const float4*>(g_partial)[(size_t)p * 524288 + i];
        s.x += v.x; s.y += v.y; s.z += v.z; s.w += v.w;
    }
    reinterpret_cast<float4*>(out)[i] = s;
}

// ---------------------------------------------------------------------------
extern "C" void kernel_launch(void* const* d_in, const int* in_sizes, int n_in,
                              void* d_out, int out_size)
{
    const float* x    = (const float*)d_in[0];   // [1024, 2, 1024]
    const float* Wenc = (const float*)d_in[1];   // [2, 1024, 32768]
    const float* benc = (const float*)d_in[2];   // [32768]
    const float* Wdec = (const float*)d_in[3];   // [2, 32768, 1024]
    const float* bdec = (const float*)d_in[4];   // [2, 1024]
    float* out = (float*)d_out;                  // [1024, 2, 1024]

    __half* gx; __half* gwe;
    cudaGetSymbolAddress((void**)&gx,  g_xh);
    cudaGetSymbolAddress((void**)&gwe, g_weh);

    cudaFuncSetAttribute(enc_kernel, cudaFuncAttributeMaxDynamicSharedMemorySize, SMEM_DYN);
    cudaFuncSetAttribute(dec_kernel, cudaFuncAttributeMaxDynamicSharedMemorySize, SMEM_DYN);

    // fp32 -> fp16 (RN): x and W_enc up front; W_dec converts inside enc's
    // extra CTA column, overlapped with the encoder GEMM.
    cvt_kernel<<<512,  256>>>(x,    gx,  (BDIM * KENC) / 8);
    cvt_kernel<<<2048, 256>>>(Wenc, gwe, (KENC * FDIM) / 8);

    enc_kernel<<<dim3(9, FDIM / 128), THREADS, SMEM_DYN>>>(benc, Wdec);
    dec_kernel<<<dim3(BDIM / 128, KENC / 128, NSPLIT), THREADS, SMEM_DYN>>>();
    reduce_kernel<<<(BDIM * KENC / 4) / 256, 256>>>(bdec, out);
}